// round 2
// baseline (speedup 1.0000x reference)
#include <cuda_runtime.h>
#include <math.h>

#define DM   2048
#define NH   16
#define DKH  128
#define NB   4
#define SEQ  2048
#define MTOT (NB*SEQ)   // 8192

// Scratch (allocation-free): Q,K,V in [B,H,S,Dk] layout, attn out in [B,S,D]
__device__ float g_q[(size_t)NB*NH*SEQ*DKH];
__device__ float g_k[(size_t)NB*NH*SEQ*DKH];
__device__ float g_v[(size_t)NB*NH*SEQ*DKH];
__device__ float g_att[(size_t)MTOT*DM];

// ---------------------------------------------------------------------------
// GEMM: C = A @ W^T.  A [M=8192, K=2048] row-major, W [N=2048, K=2048] row-major.
// Block tile 128x128, K-tile 16, 256 threads, 8x8 per-thread micro-tile.
// HEAD_LAYOUT=1: write to [B,H,S,Dk] (each 128-wide N block is one head).
// ---------------------------------------------------------------------------
template<int HEAD_LAYOUT>
__global__ __launch_bounds__(256, 2)
void gemm_xwt(const float* __restrict__ A, const float* __restrict__ W,
              float* __restrict__ C) {
    __shared__ float As[16][128];   // [k][m]
    __shared__ float Bs[16][128];   // [k][n]
    const int bm  = blockIdx.y * 128;
    const int bn  = blockIdx.x * 128;
    const int tid = threadIdx.x;
    const int ty  = tid >> 4;       // 0..15
    const int tx  = tid & 15;       // 0..15

    float acc[8][8];
#pragma unroll
    for (int i = 0; i < 8; i++)
#pragma unroll
        for (int j = 0; j < 8; j++) acc[i][j] = 0.f;

    for (int k0 = 0; k0 < DM; k0 += 16) {
#pragma unroll
        for (int i = 0; i < 2; i++) {
            int f = tid * 2 + i;          // 0..511
            int r = f >> 2;               // 0..127
            int c = (f & 3) << 2;         // {0,4,8,12}
            float4 a = *(const float4*)(A + (size_t)(bm + r) * DM + k0 + c);
            As[c + 0][r] = a.x; As[c + 1][r] = a.y;
            As[c + 2][r] = a.z; As[c + 3][r] = a.w;
            float4 b = *(const float4*)(W + (size_t)(bn + r) * DM + k0 + c);
            Bs[c + 0][r] = b.x; Bs[c + 1][r] = b.y;
            Bs[c + 2][r] = b.z; Bs[c + 3][r] = b.w;
        }
        __syncthreads();
#pragma unroll
        for (int k = 0; k < 16; k++) {
            float a[8], b[8];
            *(float4*)&a[0] = *(const float4*)&As[k][ty * 8];
            *(float4*)&a[4] = *(const float4*)&As[k][ty * 8 + 4];
            *(float4*)&b[0] = *(const float4*)&Bs[k][tx * 8];
            *(float4*)&b[4] = *(const float4*)&Bs[k][tx * 8 + 4];
#pragma unroll
            for (int i = 0; i < 8; i++)
#pragma unroll
                for (int j = 0; j < 8; j++)
                    acc[i][j] = fmaf(a[i], b[j], acc[i][j]);
        }
        __syncthreads();
    }

#pragma unroll
    for (int i = 0; i < 8; i++) {
        int m = bm + ty * 8 + i;
        float4 lo = make_float4(acc[i][0], acc[i][1], acc[i][2], acc[i][3]);
        float4 hi = make_float4(acc[i][4], acc[i][5], acc[i][6], acc[i][7]);
        if (HEAD_LAYOUT) {
            int b_  = m >> 11;            // /SEQ
            int s_  = m & (SEQ - 1);
            int h_  = bn >> 7;            // whole block is one head
            int dk0 = tx * 8;
            float* dst = C + (((size_t)(b_ * NH + h_) * SEQ + s_) * DKH) + dk0;
            *(float4*)dst       = lo;
            *(float4*)(dst + 4) = hi;
        } else {
            float* dst = C + (size_t)m * DM + bn + tx * 8;
            *(float4*)dst       = lo;
            *(float4*)(dst + 4) = hi;
        }
    }
}

// ---------------------------------------------------------------------------
// Flash attention: one CTA per (b, h, 64-row Q tile). Br=Bc=64, d=128.
// 256 threads as 16x16: ty owns 4 S-rows, tx owns 4 S-cols / 8 O-cols.
// Smem: Qs[128][64] (k-major), Ks[128][64] (k-major), Vs[64][128], Ps[64][65].
// ---------------------------------------------------------------------------
#define FLASH_SMEM_FLOATS (8192 + 8192 + 8192 + 64 * 65)
#define FLASH_SMEM_BYTES  (FLASH_SMEM_FLOATS * 4)

__global__ __launch_bounds__(256)
void flash_attn(const float* __restrict__ Q, const float* __restrict__ K,
                const float* __restrict__ V, float* __restrict__ Out) {
    extern __shared__ float sm[];
    float* Qs = sm;               // [128][64]
    float* Ks = sm + 8192;        // [128][64]
    float* Vs = sm + 16384;       // [64][128]
    float* Ps = sm + 24576;       // [64][65]

    const int tid = threadIdx.x;
    const int ty  = tid >> 4;     // 0..15 -> rows ty*4..+3
    const int tx  = tid & 15;     // 0..15 -> cols tx*4..+3 (S), tx*8..+7 (O)
    const int s0  = blockIdx.x * 64;
    const int h   = blockIdx.y;
    const int b_  = blockIdx.z;
    const size_t base = (size_t)(b_ * NH + h) * SEQ * DKH;
    const float* Qg = Q + base;
    const float* Kg = K + base;
    const float* Vg = V + base;

    const float qscale = 0.08838834764831845f;  // 1/sqrt(128)

    // Load Q tile transposed (k-major), pre-scaled.
    {
        int r  = tid >> 2;            // 0..63
        int ks = (tid & 3) * 32;      // 0/32/64/96
        const float* src = Qg + (size_t)(s0 + r) * DKH + ks;
#pragma unroll
        for (int u = 0; u < 8; u++) {
            float4 v4 = *(const float4*)(src + u * 4);
            Qs[(ks + u * 4 + 0) * 64 + r] = v4.x * qscale;
            Qs[(ks + u * 4 + 1) * 64 + r] = v4.y * qscale;
            Qs[(ks + u * 4 + 2) * 64 + r] = v4.z * qscale;
            Qs[(ks + u * 4 + 3) * 64 + r] = v4.w * qscale;
        }
    }

    float m_i[4], l_i[4], o[4][8];
#pragma unroll
    for (int i = 0; i < 4; i++) {
        m_i[i] = -1e30f; l_i[i] = 0.f;
#pragma unroll
        for (int d = 0; d < 8; d++) o[i][d] = 0.f;
    }
    __syncthreads();

    for (int j0 = 0; j0 < SEQ; j0 += 64) {
        // Load K (transposed) + V (natural)
        {
            int r  = tid >> 2;
            int ks = (tid & 3) * 32;
            const float* ksrc = Kg + (size_t)(j0 + r) * DKH + ks;
            const float* vsrc = Vg + (size_t)(j0 + r) * DKH + ks;
#pragma unroll
            for (int u = 0; u < 8; u++) {
                float4 v4 = *(const float4*)(ksrc + u * 4);
                Ks[(ks + u * 4 + 0) * 64 + r] = v4.x;
                Ks[(ks + u * 4 + 1) * 64 + r] = v4.y;
                Ks[(ks + u * 4 + 2) * 64 + r] = v4.z;
                Ks[(ks + u * 4 + 3) * 64 + r] = v4.w;
                *(float4*)&Vs[r * 128 + ks + u * 4] = *(const float4*)(vsrc + u * 4);
            }
        }
        __syncthreads();

        // S = (Q*scale) @ K^T   (4x4 per thread)
        float sc[4][4];
#pragma unroll
        for (int i = 0; i < 4; i++)
#pragma unroll
            for (int j = 0; j < 4; j++) sc[i][j] = 0.f;

#pragma unroll 4
        for (int k = 0; k < 128; k++) {
            float4 a = *(const float4*)&Qs[k * 64 + ty * 4];
            float4 b = *(const float4*)&Ks[k * 64 + tx * 4];
            float av[4] = {a.x, a.y, a.z, a.w};
            float bv[4] = {b.x, b.y, b.z, b.w};
#pragma unroll
            for (int i = 0; i < 4; i++)
#pragma unroll
                for (int j = 0; j < 4; j++)
                    sc[i][j] = fmaf(av[i], bv[j], sc[i][j]);
        }

        // Online softmax. Row i lives on the 16 lanes with equal ty
        // (lanes [0,16) or [16,32) of the warp): xor-shuffles 8..1 stay inside.
#pragma unroll
        for (int i = 0; i < 4; i++) {
            float rm = fmaxf(fmaxf(sc[i][0], sc[i][1]), fmaxf(sc[i][2], sc[i][3]));
#pragma unroll
            for (int off = 8; off; off >>= 1)
                rm = fmaxf(rm, __shfl_xor_sync(0xffffffffu, rm, off));
            float mnew = fmaxf(m_i[i], rm);
            float corr = __expf(m_i[i] - mnew);
            float rs = 0.f;
#pragma unroll
            for (int j = 0; j < 4; j++) {
                float p = __expf(sc[i][j] - mnew);
                sc[i][j] = p;
                rs += p;
            }
#pragma unroll
            for (int off = 8; off; off >>= 1)
                rs += __shfl_xor_sync(0xffffffffu, rs, off);
            l_i[i] = l_i[i] * corr + rs;
            m_i[i] = mnew;
#pragma unroll
            for (int d = 0; d < 8; d++) o[i][d] *= corr;
#pragma unroll
            for (int j = 0; j < 4; j++)
                Ps[(ty * 4 + i) * 65 + tx * 4 + j] = sc[i][j];
        }
        __syncthreads();

        // O += P @ V  (rows ty*4..+3, cols tx*8..+7)
#pragma unroll 4
        for (int j = 0; j < 64; j++) {
            float p0 = Ps[(ty * 4 + 0) * 65 + j];
            float p1 = Ps[(ty * 4 + 1) * 65 + j];
            float p2 = Ps[(ty * 4 + 2) * 65 + j];
            float p3 = Ps[(ty * 4 + 3) * 65 + j];
            float4 v0 = *(const float4*)&Vs[j * 128 + tx * 8];
            float4 v1 = *(const float4*)&Vs[j * 128 + tx * 8 + 4];
            float vv[8] = {v0.x, v0.y, v0.z, v0.w, v1.x, v1.y, v1.z, v1.w};
#pragma unroll
            for (int d = 0; d < 8; d++) {
                o[0][d] = fmaf(p0, vv[d], o[0][d]);
                o[1][d] = fmaf(p1, vv[d], o[1][d]);
                o[2][d] = fmaf(p2, vv[d], o[2][d]);
                o[3][d] = fmaf(p3, vv[d], o[3][d]);
            }
        }
        __syncthreads();
    }

    // Epilogue: Out[b, s, h*128 + dk] = o / l
#pragma unroll
    for (int i = 0; i < 4; i++) {
        float inv = 1.f / l_i[i];
        int r = s0 + ty * 4 + i;
        float* dst = Out + ((size_t)(b_ * SEQ + r)) * DM + h * DKH + tx * 8;
        *(float4*)dst = make_float4(o[i][0] * inv, o[i][1] * inv,
                                    o[i][2] * inv, o[i][3] * inv);
        *(float4*)(dst + 4) = make_float4(o[i][4] * inv, o[i][5] * inv,
                                          o[i][6] * inv, o[i][7] * inv);
    }
}

// ---------------------------------------------------------------------------
extern "C" void kernel_launch(void* const* d_in, const int* in_sizes, int n_in,
                              void* d_out, int out_size) {
    const float* x  = (const float*)d_in[0];
    const float* wq = (const float*)d_in[1];
    const float* wk = (const float*)d_in[2];
    const float* wv = (const float*)d_in[3];
    const float* wo = (const float*)d_in[4];
    float* out = (float*)d_out;

    float *q, *k, *v, *att;
    cudaGetSymbolAddress((void**)&q,   g_q);
    cudaGetSymbolAddress((void**)&k,   g_k);
    cudaGetSymbolAddress((void**)&v,   g_v);
    cudaGetSymbolAddress((void**)&att, g_att);

    cudaFuncSetAttribute(flash_attn,
                         cudaFuncAttributeMaxDynamicSharedMemorySize,
                         FLASH_SMEM_BYTES);

    dim3 gg(DM / 128, MTOT / 128);   // (16, 64)
    dim3 tt(256);

    gemm_xwt<1><<<gg, tt>>>(x, wq, q);
    gemm_xwt<1><<<gg, tt>>>(x, wk, k);
    gemm_xwt<1><<<gg, tt>>>(x, wv, v);

    dim3 fg(SEQ / 64, NH, NB);       // (32, 16, 4)
    flash_attn<<<fg, 256, FLASH_SMEM_BYTES>>>(q, k, v, att);

    gemm_xwt<0><<<gg, tt>>>(att, wo, out);
}